// round 7
// baseline (speedup 1.0000x reference)
#include <cuda_runtime.h>
#include <cuda_fp16.h>
#include <math.h>
#include <stdint.h>

#define NB 32
#define NT 512
#define NI 1024
#define NH 1024
#define NG 4096
#define GB (NG*NB)              // gate elems per step, layout [t][j'][b]
#define LOFF (4*NH*NI)
#define GRID_BLOCKS 96
#define NK16 64                 // K=1024 in 64 chunks of 16
#define B_B32 16384             // one B operand (hi or lo) in b32: 64*4*32*2
#define MAT_U4 524288           // uint4 stride per A matrix (4096x1024 fp16)
#define BUFB32 8192             // 32 KB chunk buffer (b32 units)
#define SMEM_BYTES ((3*BUFB32 + 4096 + 1024) * 4)   // 3 bufs + sTile + sC
#define PRE_SMEM 65536

// ---------------- device scratch -------------------------------------------
__device__ __align__(256) float g_xg0[(size_t)(NT + 1) * GB]; // [t][j'][b]
// A fragments fp16 (hi; lo used by pregemm only), m16n8k16 A layout.
// mat0 Wh0 [blk32][tile8][k16][lane], mat1 Wh1 / mat2 Wx1 [blk64][tile4][k16][lane],
// mat3 Wx0 [blk32][tile8][k16][lane]  (rows of mats 0-2 interleaved j'=hh*4+g)
__device__ __align__(128) __half g_Ahi[(size_t)4 * 4096 * 1024];
__device__ __align__(128) __half g_Alo[(size_t)4 * 4096 * 1024];
// seq B-fragments (hi/lo)
__device__ __align__(128) __half g_Sh[(size_t)64 * 2048 * 128];
__device__ __align__(128) __half g_Sl[(size_t)64 * 2048 * 128];
// h B-fragments, double-buffered by step parity
__device__ __align__(128) uint32_t g_B0hi[2][B_B32];
__device__ __align__(128) uint32_t g_B0lo[2][B_B32];
__device__ __align__(128) uint32_t g_B1hi[2][B_B32];
__device__ __align__(128) uint32_t g_B1lo[2][B_B32];
__device__ unsigned g_bar_count;
__device__ unsigned g_bar_gen;

// ---------------------------------------------------------------------------
__global__ void init_state() {
    int i = blockIdx.x * blockDim.x + threadIdx.x;
    int n = gridDim.x * blockDim.x;
    for (int k = i; k < B_B32; k += n) {
        g_B0hi[0][k] = 0u; g_B0lo[0][k] = 0u;
        g_B0hi[1][k] = 0u; g_B0lo[1][k] = 0u;
        g_B1hi[0][k] = 0u; g_B1lo[0][k] = 0u;
        g_B1hi[1][k] = 0u; g_B1lo[1][k] = 0u;
    }
    if (i == 0) { g_bar_count = 0; g_bar_gen = 0; }
}

// ---------------------------------------------------------------------------
__global__ __launch_bounds__(256) void prep_weights(const float* __restrict__ Wh,
                                                    const float* __restrict__ Wx) {
    size_t i = (size_t)blockIdx.x * 256 + threadIdx.x;   // 0 .. 4*4M-1
    int r = (int)(i >> 22);
    int rem = (int)(i & 4194303);
    const float* src = (r == 0) ? Wh : (r == 1) ? (Wh + LOFF)
                     : (r == 2) ? (Wx + LOFF) : Wx;
    float w = src[rem];
    __half hi = __float2half_rn(w);
    __half lo = __float2half_rn(w - __half2float(hi));
    int j = rem >> 10;           // original row g*1024+hh
    int k = rem & 1023;
    int k16 = k >> 4;
    int kc = k & 15;
    size_t frag;
    if (r == 3) {
        int blk = j >> 7, wrp = (j >> 4) & 7, row16 = j & 15;
        int lane = (row16 & 7) * 4 + ((kc & 7) >> 1);
        frag = ((size_t)(blk * 8 + wrp) * 64 + k16) * 32 + lane;
        int reg = ((kc >= 8) ? 2 : 0) + ((row16 >= 8) ? 1 : 0);
        size_t bidx = (frag * 4 + reg) * 2 + (kc & 1) + (size_t)r * 4194304;
        g_Ahi[bidx] = hi; g_Alo[bidx] = lo;
        return;
    }
    int g = j >> 10, hh = j & 1023;
    int jp = hh * 4 + g;
    int row16 = jp & 15;
    int lane = (row16 & 7) * 4 + ((kc & 7) >> 1);
    int reg = ((kc >= 8) ? 2 : 0) + ((row16 >= 8) ? 1 : 0);
    if (r == 0) {
        int blk = jp >> 7, wrp = (jp >> 4) & 7;
        frag = ((size_t)(blk * 8 + wrp) * 64 + k16) * 32 + lane;
    } else {
        int blk = jp >> 6, tile = (jp >> 4) & 3;
        frag = ((size_t)(blk * 4 + tile) * 64 + k16) * 32 + lane;
    }
    size_t bidx = (frag * 4 + reg) * 2 + (kc & 1) + (size_t)r * 4194304;
    g_Ahi[bidx] = hi; g_Alo[bidx] = lo;
}

// ---------------------------------------------------------------------------
__global__ __launch_bounds__(256) void prep_seq(const float* __restrict__ seq) {
    size_t i = (size_t)blockIdx.x * 256 + threadIdx.x;
    float v = seq[i];
    __half hi = __float2half_rn(v);
    __half lo = __float2half_rn(v - __half2float(hi));
    int b = (int)(i >> 19);
    int t = (int)(i >> 10) & 511;
    int k = (int)i & 1023;
    int c = t * 32 + b;
    int k16 = k >> 4, kc = k & 15;
    int n8 = c >> 3, nc = c & 7;
    int lane = nc * 4 + ((kc & 7) >> 1);
    int reg = (kc >= 8) ? 1 : 0;
    size_t idx = ((((size_t)k16 * 2048 + n8) * 32 + lane) * 2 + reg) * 2 + (kc & 1);
    g_Sh[idx] = hi;
    g_Sl[idx] = lo;
}

// ---------------------------------------------------------------------------
__device__ __forceinline__ void mma_f16(float* d, const uint4& a,
                                        uint32_t b0, uint32_t b1) {
    asm volatile(
        "mma.sync.aligned.m16n8k16.row.col.f32.f16.f16.f32 "
        "{%0,%1,%2,%3},{%4,%5,%6,%7},{%8,%9},{%0,%1,%2,%3};"
        : "+f"(d[0]), "+f"(d[1]), "+f"(d[2]), "+f"(d[3])
        : "r"(a.x), "r"(a.y), "r"(a.z), "r"(a.w), "r"(b0), "r"(b1));
}
__device__ __forceinline__ uint32_t smem_u32(const void* p) {
    uint32_t a;
    asm("{ .reg .u64 t; cvta.to.shared.u64 t, %1; cvt.u32.u64 %0, t; }"
        : "=r"(a) : "l"(p));
    return a;
}
__device__ __forceinline__ void cp16(uint32_t dst, const void* src) {
    asm volatile("cp.async.cg.shared.global [%0], [%1], 16;"
                 :: "r"(dst), "l"(src));
}
#define CP_COMMIT() asm volatile("cp.async.commit_group;")
#define CP_WAIT1()  asm volatile("cp.async.wait_group 1;")

// ---------------------------------------------------------------------------
// Pregemm: xg0[t][j'][b] = Wx0 @ x, fp16 hi/lo 3-pass (nt-swept to avoid
// same-acc RAW stalls). Epilogue remaps rows to j' = hh*4 + g.
// ---------------------------------------------------------------------------
__global__ __launch_bounds__(256) void pregemm_mma() {
    extern __shared__ uint32_t sm[];
    uint32_t* sBh = sm;
    uint32_t* sBl = sm + 8192;

    int tid = threadIdx.x;
    int lane = tid & 31;
    int wrp = tid >> 5;
    int blkM = blockIdx.x;
    int blkN = blockIdx.y;

    const uint4* Ah_w = (const uint4*)g_Ahi + 3 * MAT_U4 +
        (size_t)(blkM * 8 + wrp) * NK16 * 32;
    const uint4* Al_w = (const uint4*)g_Alo + 3 * MAT_U4 +
        (size_t)(blkM * 8 + wrp) * NK16 * 32;
    const uint4* gSh = (const uint4*)g_Sh;
    const uint4* gSl = (const uint4*)g_Sl;

    float acc[16][4];
#pragma unroll
    for (int nn = 0; nn < 16; nn++)
#pragma unroll
        for (int q = 0; q < 4; q++) acc[nn][q] = 0.0f;

    for (int kc8 = 0; kc8 < 8; kc8++) {
#pragma unroll
        for (int it = 0; it < 8; it++) {
            int flat = it * 256 + tid;
            int kk = flat >> 8;
            int rem = flat & 255;
            int nn = rem >> 4;
            int q = rem & 15;
            size_t srcu4 = ((size_t)(kc8 * 8 + kk) * 2048 + blkN * 16 + nn) * 16 + q;
            ((uint4*)sBh)[flat] = gSh[srcu4];
            ((uint4*)sBl)[flat] = gSl[srcu4];
        }
        __syncthreads();
#pragma unroll 2
        for (int kk = 0; kk < 8; kk++) {
            int k16 = kc8 * 8 + kk;
            uint4 ah = Ah_w[k16 * 32 + lane];
            uint4 al = Al_w[k16 * 32 + lane];
#pragma unroll
            for (int nn = 0; nn < 16; nn++) {
                int bix = ((kk * 16 + nn) * 32 + lane) * 2;
                mma_f16(acc[nn], ah, sBh[bix], sBh[bix + 1]);
            }
#pragma unroll
            for (int nn = 0; nn < 16; nn++) {
                int bix = ((kk * 16 + nn) * 32 + lane) * 2;
                mma_f16(acc[nn], ah, sBl[bix], sBl[bix + 1]);
            }
#pragma unroll
            for (int nn = 0; nn < 16; nn++) {
                int bix = ((kk * 16 + nn) * 32 + lane) * 2;
                mma_f16(acc[nn], al, sBh[bix], sBh[bix + 1]);
            }
        }
        __syncthreads();
    }
    int j0a = blkM * 128 + wrp * 16 + (lane >> 2);
    int j0b = j0a + 8;
    int ja = (j0a & 1023) * 4 + (j0a >> 10);
    int jb = (j0b & 1023) * 4 + (j0b >> 10);
    int ccl = (lane & 3) * 2;
#pragma unroll
    for (int nn = 0; nn < 16; nn++) {
        int c = blkN * 128 + nn * 8 + ccl;
        int t = c >> 5;
        int b = c & 31;
        float* base = g_xg0 + (size_t)t * GB + b;
        *(float2*)(base + (size_t)ja * 32) = make_float2(acc[nn][0], acc[nn][1]);
        *(float2*)(base + (size_t)jb * 32) = make_float2(acc[nn][2], acc[nn][3]);
    }
}

// ---------------------------------------------------------------------------
__device__ __forceinline__ float sigf(float x) {
    return 1.0f / (1.0f + __expf(-x));
}
__device__ __forceinline__ float tanhfast(float x) {
    return 2.0f / (1.0f + __expf(-2.0f * x)) - 1.0f;
}

__device__ __forceinline__ void grid_sync(unsigned& gen) {
    __syncthreads();
    if (threadIdx.x == 0) {
        unsigned target = gen + 1;
        __threadfence();
        unsigned arrived = atomicAdd(&g_bar_count, 1u);
        if (arrived == GRID_BLOCKS - 1) {
            atomicExch(&g_bar_count, 0u);
            __threadfence();
            atomicExch(&g_bar_gen, target);
        } else {
            while (*(volatile unsigned*)&g_bar_gen < target) {}
            __threadfence();
        }
        gen = target;
    }
    __syncthreads();
}

__device__ __forceinline__ void store_h_split(uint32_t* bhi, uint32_t* blo,
                                              int b, int hh, float hn) {
    int k16 = hh >> 4;
    int kc = hh & 15;
    int n8 = b >> 3;
    int nc = b & 7;
    int lane = nc * 4 + ((kc & 7) >> 1);
    int reg = (kc >= 8) ? 1 : 0;
    size_t bidx = (size_t)(((k16 * 4 + n8) * 32 + lane) * 2 + reg) * 2 + (kc & 1);
    __half hi = __float2half_rn(hn);
    __half lo = __float2half_rn(hn - __half2float(hi));
    ((__half*)bhi)[bidx] = hi;
    ((__half*)blo)[bidx] = lo;
}

// ---------------------------------------------------------------------------
// Persistent LSTM: 96 blocks x 256 threads, ONE grid barrier per step.
// cp.async triple-buffered 8-k16 chunk pipeline overlaps B staging with MMA.
//   L0 (bid 0..31):  M=128 (warp=tile of 8), K=1024, B = h0 (hi+lo per chunk).
//   L1 (bid 32..95): M=64, warp=(mat, tile): mats Wh1@h1 / Wx1@h0 run
//   concurrently; each chunk stages both B1 and B0 pieces. Partial gate sums
//   combined in sTile; fused cell update; c state resident in SMEM.
// ---------------------------------------------------------------------------
__global__ __launch_bounds__(256, 1) void lstm_persist(
    const float* __restrict__ Bias, float* __restrict__ out) {
    extern __shared__ uint32_t sm[];
    uint32_t* sBuf = sm;                         // 3 x 32 KB chunk buffers
    float* sTile = (float*)(sm + 3 * BUFB32);    // 16 KB
    float* sC = sTile + 4096;                    // 4 KB

    int tid = threadIdx.x;
    int lane = tid & 31;
    int wrp = tid >> 5;
    int bid = blockIdx.x;
    int region = (bid < 32) ? 0 : 1;
    uint32_t sbase = smem_u32(sBuf);

    unsigned gen = 0;

    if (region == 0) {
        // ------------------------------ LAYER 0 ------------------------------
        int blk = bid;
        const uint4* Ah_w = (const uint4*)g_Ahi +
            (size_t)(blk * 8 + wrp) * NK16 * 32;

        float bf[4], bw[4], bi_[4], bo[4];
#pragma unroll
        for (int i = 0; i < 4; i++) {
            int hh = blk * 32 + ((tid + i * 256) >> 5);
            bf[i] = Bias[hh]; bw[i] = Bias[1024 + hh];
            bi_[i] = Bias[2048 + hh]; bo[i] = Bias[3072 + hh];
        }

        // prologue: h0(0) = cell(c=0, xg0[0] + bias)
        {
            const float* xg = g_xg0 + (size_t)blk * 128 * 32;
#pragma unroll
            for (int i = 0; i < 4; i++) {
                int q = tid + i * 256;
                int hh_l = q >> 5, b = q & 31, br = hh_l * 4;
                float w = xg[(br + 1) * 32 + b] + bw[i];
                float i_ = xg[(br + 2) * 32 + b] + bi_[i];
                float o = xg[(br + 3) * 32 + b] + bo[i];
                float cn = sigf(w) * tanhfast(i_);
                float hn = tanhfast(cn) * sigf(o);
                sC[q] = cn;
                store_h_split(g_B0hi[0], g_B0lo[0], b, blk * 32 + hh_l, hn);
            }
        }

        for (int n = 0; n < NT; n++) {
            grid_sync(gen);
            if (n >= NT - 1) continue;          // no h0(512)
            int p = n & 1;
            const uint32_t* srcH = g_B0hi[p];
            const uint32_t* srcL = g_B0lo[p];

            // prefetch helper: chunk c = 8 k16 -> buf c%3 (hi 8KB + lo 8KB)
            auto prefetch = [&](int c) {
                uint32_t dst = sbase + ((c % 3) * BUFB32) * 4;
                int u = tid;            // 0..255 of 512 hi units
                cp16(dst + u * 16, srcH + c * 2048 + u * 4);
                cp16(dst + (u + 256) * 16, srcH + c * 2048 + (u + 256) * 4);
                cp16(dst + 8192 + u * 16, srcL + c * 2048 + u * 4);
                cp16(dst + 8192 + (u + 256) * 16, srcL + c * 2048 + (u + 256) * 4);
            };
            prefetch(0);
            CP_COMMIT();

            float acc[4][4];
#pragma unroll
            for (int nt = 0; nt < 4; nt++)
#pragma unroll
                for (int q = 0; q < 4; q++) acc[nt][q] = 0.0f;

            for (int c = 0; c < 8; c++) {
                if (c + 1 < 8) prefetch(c + 1);
                CP_COMMIT();
                CP_WAIT1();
                __syncthreads();
                const uint32_t* buf = sBuf + (c % 3) * BUFB32;
#pragma unroll
                for (int kk = 0; kk < 8; kk++) {
                    int k16 = c * 8 + kk;
                    uint4 ah = Ah_w[k16 * 32 + lane];
#pragma unroll
                    for (int nt = 0; nt < 4; nt++) {
                        int bix = kk * 256 + nt * 64 + lane * 2;
                        mma_f16(acc[nt], ah, buf[bix], buf[bix + 1]);
                    }
#pragma unroll
                    for (int nt = 0; nt < 4; nt++) {
                        int bix = 2048 + kk * 256 + nt * 64 + lane * 2;
                        mma_f16(acc[nt], ah, buf[bix], buf[bix + 1]);
                    }
                }
            }
            // epilogue -> smem tile
            int r0 = wrp * 16 + (lane >> 2);
            int cc = (lane & 3) * 2;
#pragma unroll
            for (int nt = 0; nt < 4; nt++) {
                *(float2*)&sTile[r0 * 32 + nt * 8 + cc] =
                    make_float2(acc[nt][0], acc[nt][1]);
                *(float2*)&sTile[(r0 + 8) * 32 + nt * 8 + cc] =
                    make_float2(acc[nt][2], acc[nt][3]);
            }
            __syncthreads();
            // fused cell update -> h0(n+1)
            const float* xg = g_xg0 + (size_t)(n + 1) * GB + (size_t)blk * 128 * 32;
#pragma unroll
            for (int i = 0; i < 4; i++) {
                int q = tid + i * 256;
                int hh_l = q >> 5, b = q & 31, br = hh_l * 4;
                float f = sTile[br * 32 + b] + xg[br * 32 + b] + bf[i];
                float w = sTile[(br + 1) * 32 + b] + xg[(br + 1) * 32 + b] + bw[i];
                float i_ = sTile[(br + 2) * 32 + b] + xg[(br + 2) * 32 + b] + bi_[i];
                float o = sTile[(br + 3) * 32 + b] + xg[(br + 3) * 32 + b] + bo[i];
                float cv = sC[q];
                float cn = cv * sigf(f) + sigf(w) * tanhfast(i_);
                float hn = tanhfast(cn) * sigf(o);
                sC[q] = cn;
                store_h_split(g_B0hi[1 - p], g_B0lo[1 - p], b, blk * 32 + hh_l, hn);
            }
            __syncthreads();
        }
    } else {
        // ------------------------------ LAYER 1 ------------------------------
        int blk = bid - 32;                    // 0..63, M=64
        int mat = wrp >> 2;                    // 0: Wh1 @ h1, 1: Wx1 @ h0
        int tile = wrp & 3;
        const uint4* A_w = (const uint4*)g_Ahi + (size_t)(1 + mat) * MAT_U4 +
            (size_t)(blk * 4 + tile) * NK16 * 32;

        float bf[2], bw[2], bi_[2], bo[2];
#pragma unroll
        for (int i = 0; i < 2; i++) {
            int hh = blk * 16 + ((tid + i * 256) >> 5);
            bf[i] = Bias[4096 + hh]; bw[i] = Bias[5120 + hh];
            bi_[i] = Bias[6144 + hh]; bo[i] = Bias[7168 + hh];
        }
        sC[tid] = 0.0f;
        sC[tid + 256] = 0.0f;

        for (int n = 0; n < NT; n++) {
            grid_sync(gen);
            int p = n & 1;
            const uint32_t* s1H = g_B1hi[p];
            const uint32_t* s1L = g_B1lo[p];
            const uint32_t* s0H = g_B0hi[p];
            const uint32_t* s0L = g_B0lo[p];

            // chunk c: [0:2048) B1hi, [2048:4096) B1lo,
            //          [4096:6144) B0hi, [6144:8192) B0lo
            auto prefetch = [&](int c) {
                uint32_t dst = sbase + ((c % 3) * BUFB32) * 4;
                int u = tid;
                cp16(dst + u * 16, s1H + c * 2048 + u * 4);
                cp16(dst + (u + 256) * 16, s1H + c * 2048 + (u + 256) * 4);
                cp16(dst + 8192 + u * 16, s1L + c * 2048 + u * 4);
                cp16(dst + 8192 + (u + 256) * 16, s1L + c * 2048 + (u + 256) * 4);
                cp16(dst + 16384 + u * 16, s0H + c * 2048 + u * 4);
                cp16(dst + 16384 + (u + 256) * 16, s0H + c * 2048 + (u + 256) * 4);
                cp16(dst + 24576 + u * 16, s0L + c * 2048 + u * 4);
                cp16(dst + 24576 + (u + 256) * 16, s0L + c * 2048 + (u + 256) * 4);
            };
            prefetch(0);
            CP_COMMIT();

            float acc[4][4];
#pragma unroll
            for (int nt = 0; nt < 4; nt++)
#pragma unroll
                for (int q = 0; q < 4; q++) acc[nt][q] = 0.0f;

            for (int c = 0; c < 8; c++) {
                if (c + 1 < 8) prefetch(c + 1);
                CP_COMMIT();
                CP_WAIT1();
                __syncthreads();
                const uint32_t* buf = sBuf + (c % 3) * BUFB32 + mat * 4096;
#pragma unroll
                for (int kk = 0; kk < 8; kk++) {
                    int k16 = c * 8 + kk;
                    uint4 ah = A_w[k16 * 32 + lane];
#pragma unroll
                    for (int nt = 0; nt < 4; nt++) {
                        int bix = kk * 256 + nt * 64 + lane * 2;
                        mma_f16(acc[nt], ah, buf[bix], buf[bix + 1]);
                    }
#pragma unroll
                    for (int nt = 0; nt < 4; nt++) {
                        int bix = 2048 + kk * 256 + nt * 64 + lane * 2;
                        mma_f16(acc[nt], ah, buf[bix], buf[bix + 1]);
                    }
                }
            }
            // epilogue: mat0 warps write, mat1 warps add (64x32 tile)
            int r0 = tile * 16 + (lane >> 2);
            int cc = (lane & 3) * 2;
            if (mat == 0) {
#pragma unroll
                for (int nt = 0; nt < 4; nt++) {
                    *(float2*)&sTile[r0 * 32 + nt * 8 + cc] =
                        make_float2(acc[nt][0], acc[nt][1]);
                    *(float2*)&sTile[(r0 + 8) * 32 + nt * 8 + cc] =
                        make_float2(acc[nt][2], acc[nt][3]);
                }
            }
            __syncthreads();
            if (mat == 1) {
#pragma unroll
                for (int nt = 0; nt < 4; nt++) {
                    float2* p0 = (float2*)&sTile[r0 * 32 + nt * 8 + cc];
                    float2* p1 = (float2*)&sTile[(r0 + 8) * 32 + nt * 8 + cc];
                    float2 v0 = *p0, v1 = *p1;
                    v0.x += acc[nt][0]; v0.y += acc[nt][1];
                    v1.x += acc[nt][2]; v1.y += acc[nt][3];
                    *p0 = v0; *p1 = v1;
                }
            }
            __syncthreads();
            // fused cell update -> h1(n)
#pragma unroll
            for (int i = 0; i < 2; i++) {
                int q = tid + i * 256;
                int hh_l = q >> 5, b = q & 31, br = hh_l * 4;
                float f = sTile[br * 32 + b] + bf[i];
                float w = sTile[(br + 1) * 32 + b] + bw[i];
                float i_ = sTile[(br + 2) * 32 + b] + bi_[i];
                float o = sTile[(br + 3) * 32 + b] + bo[i];
                float cv = sC[q];
                float cn = cv * sigf(f) + sigf(w) * tanhfast(i_);
                float hn = tanhfast(cn) * sigf(o);
                sC[q] = cn;
                store_h_split(g_B1hi[1 - p], g_B1lo[1 - p], b, blk * 16 + hh_l, hn);
                if (n == NT - 1) out[b * 1024 + blk * 16 + hh_l] = hn;
            }
            __syncthreads();
        }
    }
}

// ---------------------------------------------------------------------------
extern "C" void kernel_launch(void* const* d_in, const int* in_sizes, int n_in,
                              void* d_out, int out_size) {
    const float* seq  = (const float*)d_in[0];  // (32, 512, 1024)
    const float* Wh   = (const float*)d_in[1];  // (2, 4, 1024, 1024)
    const float* Wx   = (const float*)d_in[2];  // (2, 4, 1024, 1024)
    const float* Bias = (const float*)d_in[3];  // (2, 4, 1024)
    float* out = (float*)d_out;                 // (32, 1024)

    cudaFuncSetAttribute(lstm_persist,
                         cudaFuncAttributeMaxDynamicSharedMemorySize, SMEM_BYTES);
    cudaFuncSetAttribute(pregemm_mma,
                         cudaFuncAttributeMaxDynamicSharedMemorySize, PRE_SMEM);

    init_state<<<64, 256>>>();
    prep_weights<<<4 * 4096 * 1024 / 256, 256>>>(Wh, Wx);
    prep_seq<<<NB * NT * NI / 256, 256>>>(seq);
    pregemm_mma<<<dim3(32, 128), 256, PRE_SMEM>>>();
    lstm_persist<<<GRID_BLOCKS, 256, SMEM_BYTES>>>(Bias, out);
}

// round 8
// speedup vs baseline: 1.4360x; 1.4360x over previous
#include <cuda_runtime.h>
#include <cuda_fp16.h>
#include <math.h>
#include <stdint.h>

#define NB 32
#define NT 512
#define NI 1024
#define NH 1024
#define NG 4096
#define GB (NG*NB)              // gate elems per step, layout [t][j'][b]
#define LOFF (4*NH*NI)
#define GRID_BLOCKS 128
#define NK16 64                 // K=1024 in 64 chunks of 16
#define B_B32 16384             // one B vector in b32: 64*4*32*2 (fp16 single)
#define MAT_U4 524288           // uint4 stride per A matrix (4096x1024 fp16)
// smem: sA 8192 u4 (128K) + sB 16384 b32 (64K) + sTile 2048 f (8K) + sC 512 f (2K)
#define SMEM_BYTES (131072 + 65536 + 8192 + 2048)
#define PRE_SMEM 65536

// ---------------- device scratch -------------------------------------------
__device__ __align__(256) float g_xg0[(size_t)(NT + 1) * GB]; // [t][j'][b]
// A fragments fp16 in m16n8k16 A layout.
// mats 0-2 (Wh0, Wh1, Wx1): interleaved rows j'=hh*4+g, [blk64][tile4][k16][lane]
// mat 3 (Wx0, pregemm): original rows, [blk32][warp8][k16][lane]
__device__ __align__(128) __half g_Ahi[(size_t)4 * 4096 * 1024];
__device__ __align__(128) __half g_Alo[(size_t)4 * 4096 * 1024];
// seq B-fragments (hi/lo, pregemm)
__device__ __align__(128) __half g_Sh[(size_t)64 * 2048 * 128];
__device__ __align__(128) __half g_Sl[(size_t)64 * 2048 * 128];
// h B-fragments (single fp16), double-buffered by step parity
__device__ __align__(128) uint32_t g_B0[2][B_B32];
__device__ __align__(128) uint32_t g_B1[2][B_B32];
__device__ unsigned g_bar_count;
__device__ unsigned g_bar_gen;

// ---------------------------------------------------------------------------
__global__ void init_state() {
    int i = blockIdx.x * blockDim.x + threadIdx.x;
    int n = gridDim.x * blockDim.x;
    for (int k = i; k < B_B32; k += n) {
        g_B0[0][k] = 0u; g_B0[1][k] = 0u;
        g_B1[0][k] = 0u; g_B1[1][k] = 0u;
    }
    if (i == 0) { g_bar_count = 0; g_bar_gen = 0; }
}

// ---------------------------------------------------------------------------
__global__ __launch_bounds__(256) void prep_weights(const float* __restrict__ Wh,
                                                    const float* __restrict__ Wx) {
    size_t i = (size_t)blockIdx.x * 256 + threadIdx.x;   // 0 .. 4*4M-1
    int r = (int)(i >> 22);
    int rem = (int)(i & 4194303);
    const float* src = (r == 0) ? Wh : (r == 1) ? (Wh + LOFF)
                     : (r == 2) ? (Wx + LOFF) : Wx;
    float w = src[rem];
    __half hi = __float2half_rn(w);
    __half lo = __float2half_rn(w - __half2float(hi));
    int j = rem >> 10;           // original row g*1024+hh
    int k = rem & 1023;
    int k16 = k >> 4;
    int kc = k & 15;
    size_t frag;
    if (r == 3) {
        int blk = j >> 7, wrp = (j >> 4) & 7, row16 = j & 15;
        int lane = (row16 & 7) * 4 + ((kc & 7) >> 1);
        frag = ((size_t)(blk * 8 + wrp) * 64 + k16) * 32 + lane;
        int reg = ((kc >= 8) ? 2 : 0) + ((row16 >= 8) ? 1 : 0);
        size_t bidx = (frag * 4 + reg) * 2 + (kc & 1) + (size_t)r * 4194304;
        g_Ahi[bidx] = hi; g_Alo[bidx] = lo;
        return;
    }
    int g = j >> 10, hh = j & 1023;
    int jp = hh * 4 + g;
    int row16 = jp & 15;
    int lane = (row16 & 7) * 4 + ((kc & 7) >> 1);
    int reg = ((kc >= 8) ? 2 : 0) + ((row16 >= 8) ? 1 : 0);
    int blk = jp >> 6, tile = (jp >> 4) & 3;
    frag = ((size_t)(blk * 4 + tile) * 64 + k16) * 32 + lane;
    size_t bidx = (frag * 4 + reg) * 2 + (kc & 1) + (size_t)r * 4194304;
    g_Ahi[bidx] = hi; g_Alo[bidx] = lo;
}

// ---------------------------------------------------------------------------
__global__ __launch_bounds__(256) void prep_seq(const float* __restrict__ seq) {
    size_t i = (size_t)blockIdx.x * 256 + threadIdx.x;
    float v = seq[i];
    __half hi = __float2half_rn(v);
    __half lo = __float2half_rn(v - __half2float(hi));
    int b = (int)(i >> 19);
    int t = (int)(i >> 10) & 511;
    int k = (int)i & 1023;
    int c = t * 32 + b;
    int k16 = k >> 4, kc = k & 15;
    int n8 = c >> 3, nc = c & 7;
    int lane = nc * 4 + ((kc & 7) >> 1);
    int reg = (kc >= 8) ? 1 : 0;
    size_t idx = ((((size_t)k16 * 2048 + n8) * 32 + lane) * 2 + reg) * 2 + (kc & 1);
    g_Sh[idx] = hi;
    g_Sl[idx] = lo;
}

// ---------------------------------------------------------------------------
__device__ __forceinline__ void mma_f16(float* d, const uint4& a,
                                        uint32_t b0, uint32_t b1) {
    asm volatile(
        "mma.sync.aligned.m16n8k16.row.col.f32.f16.f16.f32 "
        "{%0,%1,%2,%3},{%4,%5,%6,%7},{%8,%9},{%0,%1,%2,%3};"
        : "+f"(d[0]), "+f"(d[1]), "+f"(d[2]), "+f"(d[3])
        : "r"(a.x), "r"(a.y), "r"(a.z), "r"(a.w), "r"(b0), "r"(b1));
}
__device__ __forceinline__ uint32_t smem_u32(const void* p) {
    uint32_t a;
    asm("{ .reg .u64 t; cvta.to.shared.u64 t, %1; cvt.u32.u64 %0, t; }"
        : "=r"(a) : "l"(p));
    return a;
}
__device__ __forceinline__ void cp16(uint32_t dst, const void* src) {
    asm volatile("cp.async.cg.shared.global [%0], [%1], 16;"
                 :: "r"(dst), "l"(src));
}
#define CP_COMMIT() asm volatile("cp.async.commit_group;")
#define CP_WAIT0()  asm volatile("cp.async.wait_group 0;")

// ---------------------------------------------------------------------------
// Pregemm: xg0[t][j'][b] = Wx0 @ x, fp16 hi/lo 3-pass. Rows remapped to j'.
// ---------------------------------------------------------------------------
__global__ __launch_bounds__(256) void pregemm_mma() {
    extern __shared__ uint32_t sm[];
    uint32_t* sBh = sm;
    uint32_t* sBl = sm + 8192;

    int tid = threadIdx.x;
    int lane = tid & 31;
    int wrp = tid >> 5;
    int blkM = blockIdx.x;
    int blkN = blockIdx.y;

    const uint4* Ah_w = (const uint4*)g_Ahi + 3 * MAT_U4 +
        (size_t)(blkM * 8 + wrp) * NK16 * 32;
    const uint4* Al_w = (const uint4*)g_Alo + 3 * MAT_U4 +
        (size_t)(blkM * 8 + wrp) * NK16 * 32;
    const uint4* gSh = (const uint4*)g_Sh;
    const uint4* gSl = (const uint4*)g_Sl;

    float acc[16][4];
#pragma unroll
    for (int nn = 0; nn < 16; nn++)
#pragma unroll
        for (int q = 0; q < 4; q++) acc[nn][q] = 0.0f;

    for (int kc8 = 0; kc8 < 8; kc8++) {
#pragma unroll
        for (int it = 0; it < 8; it++) {
            int flat = it * 256 + tid;
            int kk = flat >> 8;
            int rem = flat & 255;
            int nn = rem >> 4;
            int q = rem & 15;
            size_t srcu4 = ((size_t)(kc8 * 8 + kk) * 2048 + blkN * 16 + nn) * 16 + q;
            ((uint4*)sBh)[flat] = gSh[srcu4];
            ((uint4*)sBl)[flat] = gSl[srcu4];
        }
        __syncthreads();
#pragma unroll 2
        for (int kk = 0; kk < 8; kk++) {
            int k16 = kc8 * 8 + kk;
            uint4 ah = Ah_w[k16 * 32 + lane];
            uint4 al = Al_w[k16 * 32 + lane];
#pragma unroll
            for (int nn = 0; nn < 16; nn++) {
                int bix = ((kk * 16 + nn) * 32 + lane) * 2;
                mma_f16(acc[nn], ah, sBh[bix], sBh[bix + 1]);
            }
#pragma unroll
            for (int nn = 0; nn < 16; nn++) {
                int bix = ((kk * 16 + nn) * 32 + lane) * 2;
                mma_f16(acc[nn], ah, sBl[bix], sBl[bix + 1]);
            }
#pragma unroll
            for (int nn = 0; nn < 16; nn++) {
                int bix = ((kk * 16 + nn) * 32 + lane) * 2;
                mma_f16(acc[nn], al, sBh[bix], sBh[bix + 1]);
            }
        }
        __syncthreads();
    }
    int j0a = blkM * 128 + wrp * 16 + (lane >> 2);
    int j0b = j0a + 8;
    int ja = (j0a & 1023) * 4 + (j0a >> 10);
    int jb = (j0b & 1023) * 4 + (j0b >> 10);
    int ccl = (lane & 3) * 2;
#pragma unroll
    for (int nn = 0; nn < 16; nn++) {
        int c = blkN * 128 + nn * 8 + ccl;
        int t = c >> 5;
        int b = c & 31;
        float* base = g_xg0 + (size_t)t * GB + b;
        *(float2*)(base + (size_t)ja * 32) = make_float2(acc[nn][0], acc[nn][1]);
        *(float2*)(base + (size_t)jb * 32) = make_float2(acc[nn][2], acc[nn][3]);
    }
}

// ---------------------------------------------------------------------------
__device__ __forceinline__ float sigf(float x) {
    return 1.0f / (1.0f + __expf(-x));
}
__device__ __forceinline__ float tanhfast(float x) {
    return 2.0f / (1.0f + __expf(-2.0f * x)) - 1.0f;
}

__device__ __forceinline__ void grid_sync(unsigned& gen) {
    __syncthreads();
    if (threadIdx.x == 0) {
        unsigned target = gen + 1;
        __threadfence();
        unsigned arrived = atomicAdd(&g_bar_count, 1u);
        if (arrived == GRID_BLOCKS - 1) {
            atomicExch(&g_bar_count, 0u);
            __threadfence();
            atomicExch(&g_bar_gen, target);
        } else {
            while (*(volatile unsigned*)&g_bar_gen < target) {}
            __threadfence();
        }
        gen = target;
    }
    __syncthreads();
}

// write h (single fp16) into B-fragment layout
__device__ __forceinline__ void store_h(uint32_t* bdst, int b, int hh, float hn) {
    int k16 = hh >> 4;
    int kc = hh & 15;
    int n8 = b >> 3;
    int nc = b & 7;
    int lane = nc * 4 + ((kc & 7) >> 1);
    int reg = (kc >= 8) ? 1 : 0;
    size_t bidx = (size_t)(((k16 * 4 + n8) * 32 + lane) * 2 + reg) * 2 + (kc & 1);
    ((__half*)bdst)[bidx] = __float2half_rn(hn);
}

// ---------------------------------------------------------------------------
// Persistent LSTM: 128 blocks x 256 threads, one grid barrier per step.
//   L0 (bid 0..63):  M=64 (16 hh), K=1024, A=Wh0 PINNED IN SMEM, B=h0 staged.
//                    warps (khalf, tile): K split in halves, combined in sTile.
//   L1 (bid 64..127): M=64 (16 hh), warps (mat, tile): Wh1 (SMEM-pinned) @ h1
//                    and Wx1 (streamed) @ h0 concurrently, K in 2 staged halves.
// Fused cell update per block; c state in SMEM; h double-buffered in gmem.
// ---------------------------------------------------------------------------
__global__ __launch_bounds__(256, 1) void lstm_persist(
    const float* __restrict__ Bias, float* __restrict__ out) {
    extern __shared__ uint32_t sm[];
    uint4* sA = (uint4*)sm;                      // 8192 u4 = 128 KB pinned A
    uint32_t* sB = sm + 32768;                   // 16384 b32 = 64 KB
    float* sTile = (float*)(sm + 49152);         // 2048 f32
    float* sC = sTile + 2048;                    // 512 f32

    int tid = threadIdx.x;
    int lane = tid & 31;
    int wrp = tid >> 5;
    int bid = blockIdx.x;
    int region = (bid < 64) ? 0 : 1;
    int blk = bid & 63;
    uint32_t sBaddr = smem_u32(sB);

    // preload pinned A slice (mat0 for L0, mat1=Wh1 for L1), 8192 uint4
    {
        const uint4* Apin = (const uint4*)g_Ahi +
            (size_t)region * MAT_U4 + (size_t)(blk * 4) * NK16 * 32;
        for (int i = tid; i < 8192; i += 256) sA[i] = Apin[i];
    }

    float bf[2], bw[2], bi_[2], bo[2];
#pragma unroll
    for (int i = 0; i < 2; i++) {
        int hh = blk * 16 + ((tid + i * 256) >> 5);
        int boff = region * 4096;
        bf[i] = Bias[boff + hh];        bw[i] = Bias[boff + 1024 + hh];
        bi_[i] = Bias[boff + 2048 + hh]; bo[i] = Bias[boff + 3072 + hh];
    }

    unsigned gen = 0;

    if (region == 0) {
        // prologue: h0(0) = cell(c=0, xg0[0] + bias) -> g_B0[0]
        const float* xg = g_xg0 + (size_t)(blk * 64) * 32;
#pragma unroll
        for (int i = 0; i < 2; i++) {
            int q = tid + i * 256;
            int hh_l = q >> 5, b = q & 31, br = hh_l * 4;
            float w = xg[(br + 1) * 32 + b] + bw[i];
            float i_ = xg[(br + 2) * 32 + b] + bi_[i];
            float o = xg[(br + 3) * 32 + b] + bo[i];
            float cn = sigf(w) * tanhfast(i_);
            float hn = tanhfast(cn) * sigf(o);
            sC[q] = cn;
            store_h(g_B0[0], b, blk * 16 + hh_l, hn);
        }
    } else {
#pragma unroll
        for (int i = 0; i < 2; i++) sC[tid + i * 256] = 0.0f;
    }
    __syncthreads();

    int tile = wrp & 3;
    int sel = wrp >> 2;        // L0: khalf ; L1: mat (0=Wh1@h1, 1=Wx1@h0)

    if (region == 0) {
        // ------------------------------ LAYER 0 ------------------------------
        for (int n = 0; n < NT; n++) {
            grid_sync(gen);
            if (n >= NT - 1) continue;          // no h0(512) needed
            int p = n & 1;

            // prefetch next-step input gates into registers (hide DRAM)
            float xr[8];
            {
                const float* xg = g_xg0 + (size_t)(n + 1) * GB + (size_t)(blk * 64) * 32;
#pragma unroll
                for (int i = 0; i < 2; i++) {
                    int q = tid + i * 256;
                    int b = q & 31, br = (q >> 5) * 4;
#pragma unroll
                    for (int g = 0; g < 4; g++)
                        xr[i * 4 + g] = xg[(br + g) * 32 + b];
                }
            }
            // stage h0(n) fragments (64 KB)
            {
                const uint32_t* src = g_B0[p];
#pragma unroll
                for (int i = 0; i < 16; i++) {
                    int u = tid + i * 256;
                    cp16(sBaddr + u * 16, src + u * 4);
                }
                CP_COMMIT();
                CP_WAIT0();
            }
            __syncthreads();

            float acc[4][4];
#pragma unroll
            for (int nt = 0; nt < 4; nt++)
#pragma unroll
                for (int q = 0; q < 4; q++) acc[nt][q] = 0.0f;
#pragma unroll 8
            for (int kk = 0; kk < 32; kk++) {
                int k16 = sel * 32 + kk;
                uint4 a = sA[(tile * 64 + k16) * 32 + lane];
#pragma unroll
                for (int nt = 0; nt < 4; nt++) {
                    int bix = (k16 * 4 + nt) * 64 + lane * 2;
                    mma_f16(acc[nt], a, sB[bix], sB[bix + 1]);
                }
            }
            // combine K-halves in sTile
            int r0 = tile * 16 + (lane >> 2);
            int cc = (lane & 3) * 2;
            if (sel == 0) {
#pragma unroll
                for (int nt = 0; nt < 4; nt++) {
                    *(float2*)&sTile[r0 * 32 + nt * 8 + cc] =
                        make_float2(acc[nt][0], acc[nt][1]);
                    *(float2*)&sTile[(r0 + 8) * 32 + nt * 8 + cc] =
                        make_float2(acc[nt][2], acc[nt][3]);
                }
            }
            __syncthreads();
            if (sel == 1) {
#pragma unroll
                for (int nt = 0; nt < 4; nt++) {
                    float2* p0 = (float2*)&sTile[r0 * 32 + nt * 8 + cc];
                    float2* p1 = (float2*)&sTile[(r0 + 8) * 32 + nt * 8 + cc];
                    float2 v0 = *p0, v1 = *p1;
                    v0.x += acc[nt][0]; v0.y += acc[nt][1];
                    v1.x += acc[nt][2]; v1.y += acc[nt][3];
                    *p0 = v0; *p1 = v1;
                }
            }
            __syncthreads();
            // fused cell update -> h0(n+1)
#pragma unroll
            for (int i = 0; i < 2; i++) {
                int q = tid + i * 256;
                int hh_l = q >> 5, b = q & 31, br = hh_l * 4;
                float f = sTile[br * 32 + b] + xr[i * 4 + 0] + bf[i];
                float w = sTile[(br + 1) * 32 + b] + xr[i * 4 + 1] + bw[i];
                float i_ = sTile[(br + 2) * 32 + b] + xr[i * 4 + 2] + bi_[i];
                float o = sTile[(br + 3) * 32 + b] + xr[i * 4 + 3] + bo[i];
                float cv = sC[q];
                float cn = cv * sigf(f) + sigf(w) * tanhfast(i_);
                float hn = tanhfast(cn) * sigf(o);
                sC[q] = cn;
                store_h(g_B0[1 - p], b, blk * 16 + hh_l, hn);
            }
            __syncthreads();
        }
    } else {
        // ------------------------------ LAYER 1 ------------------------------
        const uint4* A2 = (const uint4*)g_Ahi + 2 * MAT_U4 +
            (size_t)(blk * 4 + tile) * NK16 * 32;   // Wx1 streamed

        for (int n = 0; n < NT; n++) {
            grid_sync(gen);
            int p = n & 1;

            float acc[4][4];
#pragma unroll
            for (int nt = 0; nt < 4; nt++)
#pragma unroll
                for (int q = 0; q < 4; q++) acc[nt][q] = 0.0f;

            for (int h2 = 0; h2 < 2; h2++) {
                // stage K-half: h1 frag -> sB[0:8192), h0 frag -> sB[8192:16384)
                {
                    const uint32_t* s1 = g_B1[p] + h2 * 8192;
                    const uint32_t* s0 = g_B0[p] + h2 * 8192;
#pragma unroll
                    for (int i = 0; i < 8; i++) {
                        int u = tid + i * 256;
                        cp16(sBaddr + u * 16, s1 + u * 4);
                        cp16(sBaddr + 32768 + u * 16, s0 + u * 4);
                    }
                    CP_COMMIT();
                    CP_WAIT0();
                }
                __syncthreads();
                const uint32_t* myB = sB + sel * 8192;
#pragma unroll 8
                for (int kk = 0; kk < 32; kk++) {
                    int k16 = h2 * 32 + kk;
                    uint4 a = (sel == 0) ? sA[(tile * 64 + k16) * 32 + lane]
                                         : A2[k16 * 32 + lane];
#pragma unroll
                    for (int nt = 0; nt < 4; nt++) {
                        int bix = (kk * 4 + nt) * 64 + lane * 2;
                        mma_f16(acc[nt], a, myB[bix], myB[bix + 1]);
                    }
                }
                __syncthreads();               // buffer reused next half
            }
            // combine the two matrices in sTile
            int r0 = tile * 16 + (lane >> 2);
            int cc = (lane & 3) * 2;
            if (sel == 0) {
#pragma unroll
                for (int nt = 0; nt < 4; nt++) {
                    *(float2*)&sTile[r0 * 32 + nt * 8 + cc] =
                        make_float2(acc[nt][0], acc[nt][1]);
                    *(float2*)&sTile[(r0 + 8) * 32 + nt * 8 + cc] =
                        make_float2(acc[nt][2], acc[nt][3]);
                }
            }
            __syncthreads();
            if (sel == 1) {
#pragma unroll
                for (int nt = 0; nt < 4; nt++) {
                    float2* p0 = (float2*)&sTile[r0 * 32 + nt * 8 + cc];
                    float2* p1 = (float2*)&sTile[(r0 + 8) * 32 + nt * 8 + cc];
                    float2 v0 = *p0, v1 = *p1;
                    v0.x += acc[nt][0]; v0.y += acc[nt][1];
                    v1.x += acc[nt][2]; v1.y += acc[nt][3];
                    *p0 = v0; *p1 = v1;
                }
            }
            __syncthreads();
            // fused cell update -> h1(n)
#pragma unroll
            for (int i = 0; i < 2; i++) {
                int q = tid + i * 256;
                int hh_l = q >> 5, b = q & 31, br = hh_l * 4;
                float f = sTile[br * 32 + b] + bf[i];
                float w = sTile[(br + 1) * 32 + b] + bw[i];
                float i_ = sTile[(br + 2) * 32 + b] + bi_[i];
                float o = sTile[(br + 3) * 32 + b] + bo[i];
                float cv = sC[q];
                float cn = cv * sigf(f) + sigf(w) * tanhfast(i_);
                float hn = tanhfast(cn) * sigf(o);
                sC[q] = cn;
                store_h(g_B1[1 - p], b, blk * 16 + hh_l, hn);
                if (n == NT - 1) out[b * 1024 + blk * 16 + hh_l] = hn;
            }
            __syncthreads();
        }
    }
}

// ---------------------------------------------------------------------------
extern "C" void kernel_launch(void* const* d_in, const int* in_sizes, int n_in,
                              void* d_out, int out_size) {
    const float* seq  = (const float*)d_in[0];  // (32, 512, 1024)
    const float* Wh   = (const float*)d_in[1];  // (2, 4, 1024, 1024)
    const float* Wx   = (const float*)d_in[2];  // (2, 4, 1024, 1024)
    const float* Bias = (const float*)d_in[3];  // (2, 4, 1024)
    float* out = (float*)d_out;                 // (32, 1024)

    cudaFuncSetAttribute(lstm_persist,
                         cudaFuncAttributeMaxDynamicSharedMemorySize, SMEM_BYTES);
    cudaFuncSetAttribute(pregemm_mma,
                         cudaFuncAttributeMaxDynamicSharedMemorySize, PRE_SMEM);

    init_state<<<64, 256>>>();
    prep_weights<<<4 * 4096 * 1024 / 256, 256>>>(Wh, Wx);
    prep_seq<<<NB * NT * NI / 256, 256>>>(seq);
    pregemm_mma<<<dim3(32, 128), 256, PRE_SMEM>>>();
    lstm_persist<<<GRID_BLOCKS, 256, SMEM_BYTES>>>(Bias, out);
}

// round 9
// speedup vs baseline: 1.4784x; 1.0295x over previous
#include <cuda_runtime.h>
#include <cuda_fp16.h>
#include <math.h>
#include <stdint.h>

#define NB 32
#define NT 512
#define NI 1024
#define NH 1024
#define NG 4096
#define GB (NG*NB)              // gate elems per step, layout [t][j'][b]
#define LOFF (4*NH*NI)
#define GRID_BLOCKS 128
#define NK16 64                 // K=1024 in 64 chunks of 16
#define B_B32 16384             // one B vector in b32: 64*4*32*2 (fp16 single)
#define MAT_U4 524288           // uint4 stride per A matrix (4096x1024 fp16)
// smem: sA 8192 u4 (128K) + sB 16384 b32 (64K) + sTile 2048 f (8K) + sC 512 f (2K)
#define SMEM_BYTES (131072 + 65536 + 8192 + 2048)
#define PRE_SMEM 32768

// ---------------- device scratch -------------------------------------------
__device__ __align__(256) float g_xg0[(size_t)(NT + 1) * GB]; // [t][j'][b]
// A fragments fp16 in m16n8k16 A layout.
// mats 0-2 (Wh0, Wh1, Wx1): interleaved rows j'=hh*4+g, [blk64][tile4][k16][lane]
// mat 3 (Wx0, pregemm): original rows, [blk32][warp8][k16][lane]
__device__ __align__(128) __half g_Ahi[(size_t)4 * 4096 * 1024];
__device__ __align__(128) __half g_Alo[(size_t)4 * 4096 * 1024];
// seq B-fragments (hi only; B treated as single fp16 in pregemm)
__device__ __align__(128) __half g_Sh[(size_t)64 * 2048 * 128];
// h B-fragments (single fp16), double-buffered by step parity
__device__ __align__(128) uint32_t g_B0[2][B_B32];
__device__ __align__(128) uint32_t g_B1[2][B_B32];
__device__ unsigned g_bar_count;
__device__ unsigned g_bar_gen;

// ---------------------------------------------------------------------------
__global__ void init_state() {
    int i = blockIdx.x * blockDim.x + threadIdx.x;
    int n = gridDim.x * blockDim.x;
    for (int k = i; k < B_B32; k += n) {
        g_B0[0][k] = 0u; g_B0[1][k] = 0u;
        g_B1[0][k] = 0u; g_B1[1][k] = 0u;
    }
    if (i == 0) { g_bar_count = 0; g_bar_gen = 0; }
}

// ---------------------------------------------------------------------------
__global__ __launch_bounds__(256) void prep_weights(const float* __restrict__ Wh,
                                                    const float* __restrict__ Wx) {
    size_t i = (size_t)blockIdx.x * 256 + threadIdx.x;   // 0 .. 4*4M-1
    int r = (int)(i >> 22);
    int rem = (int)(i & 4194303);
    const float* src = (r == 0) ? Wh : (r == 1) ? (Wh + LOFF)
                     : (r == 2) ? (Wx + LOFF) : Wx;
    float w = src[rem];
    __half hi = __float2half_rn(w);
    __half lo = __float2half_rn(w - __half2float(hi));
    int j = rem >> 10;           // original row g*1024+hh
    int k = rem & 1023;
    int k16 = k >> 4;
    int kc = k & 15;
    size_t frag;
    if (r == 3) {
        int blk = j >> 7, wrp = (j >> 4) & 7, row16 = j & 15;
        int lane = (row16 & 7) * 4 + ((kc & 7) >> 1);
        frag = ((size_t)(blk * 8 + wrp) * 64 + k16) * 32 + lane;
        int reg = ((kc >= 8) ? 2 : 0) + ((row16 >= 8) ? 1 : 0);
        size_t bidx = (frag * 4 + reg) * 2 + (kc & 1) + (size_t)r * 4194304;
        g_Ahi[bidx] = hi; g_Alo[bidx] = lo;
        return;
    }
    int g = j >> 10, hh = j & 1023;
    int jp = hh * 4 + g;
    int row16 = jp & 15;
    int lane = (row16 & 7) * 4 + ((kc & 7) >> 1);
    int reg = ((kc >= 8) ? 2 : 0) + ((row16 >= 8) ? 1 : 0);
    int blk = jp >> 6, tile = (jp >> 4) & 3;
    frag = ((size_t)(blk * 4 + tile) * 64 + k16) * 32 + lane;
    size_t bidx = (frag * 4 + reg) * 2 + (kc & 1) + (size_t)r * 4194304;
    g_Ahi[bidx] = hi; g_Alo[bidx] = lo;
}

// ---------------------------------------------------------------------------
__global__ __launch_bounds__(256) void prep_seq(const float* __restrict__ seq) {
    size_t i = (size_t)blockIdx.x * 256 + threadIdx.x;
    float v = seq[i];
    __half hi = __float2half_rn(v);
    int b = (int)(i >> 19);
    int t = (int)(i >> 10) & 511;
    int k = (int)i & 1023;
    int c = t * 32 + b;
    int k16 = k >> 4, kc = k & 15;
    int n8 = c >> 3, nc = c & 7;
    int lane = nc * 4 + ((kc & 7) >> 1);
    int reg = (kc >= 8) ? 1 : 0;
    size_t idx = ((((size_t)k16 * 2048 + n8) * 32 + lane) * 2 + reg) * 2 + (kc & 1);
    g_Sh[idx] = hi;
}

// ---------------------------------------------------------------------------
__device__ __forceinline__ void mma_f16(float* d, const uint4& a,
                                        uint32_t b0, uint32_t b1) {
    asm volatile(
        "mma.sync.aligned.m16n8k16.row.col.f32.f16.f16.f32 "
        "{%0,%1,%2,%3},{%4,%5,%6,%7},{%8,%9},{%0,%1,%2,%3};"
        : "+f"(d[0]), "+f"(d[1]), "+f"(d[2]), "+f"(d[3])
        : "r"(a.x), "r"(a.y), "r"(a.z), "r"(a.w), "r"(b0), "r"(b1));
}
__device__ __forceinline__ uint32_t smem_u32(const void* p) {
    uint32_t a;
    asm("{ .reg .u64 t; cvta.to.shared.u64 t, %1; cvt.u32.u64 %0, t; }"
        : "=r"(a) : "l"(p));
    return a;
}
__device__ __forceinline__ void cp16(uint32_t dst, const void* src) {
    asm volatile("cp.async.cg.shared.global [%0], [%1], 16;"
                 :: "r"(dst), "l"(src));
}
#define CP_COMMIT() asm volatile("cp.async.commit_group;")
#define CP_WAIT0()  asm volatile("cp.async.wait_group 0;")
#define CP_WAIT1()  asm volatile("cp.async.wait_group 1;")

// ---------------------------------------------------------------------------
// Pregemm: xg0[t][j'][b] = Wx0 @ x, fp16 2-pass (A hi/lo, B single fp16).
// Rows remapped to j' = hh*4 + g.
// ---------------------------------------------------------------------------
__global__ __launch_bounds__(256) void pregemm_mma() {
    extern __shared__ uint32_t sm[];
    uint32_t* sBh = sm;

    int tid = threadIdx.x;
    int lane = tid & 31;
    int wrp = tid >> 5;
    int blkM = blockIdx.x;
    int blkN = blockIdx.y;

    const uint4* Ah_w = (const uint4*)g_Ahi + 3 * MAT_U4 +
        (size_t)(blkM * 8 + wrp) * NK16 * 32;
    const uint4* Al_w = (const uint4*)g_Alo + 3 * MAT_U4 +
        (size_t)(blkM * 8 + wrp) * NK16 * 32;
    const uint4* gSh = (const uint4*)g_Sh;

    float acc[16][4];
#pragma unroll
    for (int nn = 0; nn < 16; nn++)
#pragma unroll
        for (int q = 0; q < 4; q++) acc[nn][q] = 0.0f;

    for (int kc8 = 0; kc8 < 8; kc8++) {
#pragma unroll
        for (int it = 0; it < 8; it++) {
            int flat = it * 256 + tid;
            int kk = flat >> 8;
            int rem = flat & 255;
            int nn = rem >> 4;
            int q = rem & 15;
            size_t srcu4 = ((size_t)(kc8 * 8 + kk) * 2048 + blkN * 16 + nn) * 16 + q;
            ((uint4*)sBh)[flat] = gSh[srcu4];
        }
        __syncthreads();
#pragma unroll 2
        for (int kk = 0; kk < 8; kk++) {
            int k16 = kc8 * 8 + kk;
            uint4 ah = Ah_w[k16 * 32 + lane];
            uint4 al = Al_w[k16 * 32 + lane];
#pragma unroll
            for (int nn = 0; nn < 16; nn++) {
                int bix = ((kk * 16 + nn) * 32 + lane) * 2;
                mma_f16(acc[nn], ah, sBh[bix], sBh[bix + 1]);
            }
#pragma unroll
            for (int nn = 0; nn < 16; nn++) {
                int bix = ((kk * 16 + nn) * 32 + lane) * 2;
                mma_f16(acc[nn], al, sBh[bix], sBh[bix + 1]);
            }
        }
        __syncthreads();
    }
    int j0a = blkM * 128 + wrp * 16 + (lane >> 2);
    int j0b = j0a + 8;
    int ja = (j0a & 1023) * 4 + (j0a >> 10);
    int jb = (j0b & 1023) * 4 + (j0b >> 10);
    int ccl = (lane & 3) * 2;
#pragma unroll
    for (int nn = 0; nn < 16; nn++) {
        int c = blkN * 128 + nn * 8 + ccl;
        int t = c >> 5;
        int b = c & 31;
        float* base = g_xg0 + (size_t)t * GB + b;
        *(float2*)(base + (size_t)ja * 32) = make_float2(acc[nn][0], acc[nn][1]);
        *(float2*)(base + (size_t)jb * 32) = make_float2(acc[nn][2], acc[nn][3]);
    }
}

// ---------------------------------------------------------------------------
__device__ __forceinline__ float sigf(float x) {
    return 1.0f / (1.0f + __expf(-x));
}
__device__ __forceinline__ float tanhfast(float x) {
    return 2.0f / (1.0f + __expf(-2.0f * x)) - 1.0f;
}

__device__ __forceinline__ void grid_sync(unsigned& gen) {
    __syncthreads();
    if (threadIdx.x == 0) {
        unsigned target = gen + 1;
        __threadfence();
        unsigned arrived = atomicAdd(&g_bar_count, 1u);
        if (arrived == GRID_BLOCKS - 1) {
            atomicExch(&g_bar_count, 0u);
            __threadfence();
            atomicExch(&g_bar_gen, target);
        } else {
            while (*(volatile unsigned*)&g_bar_gen < target) {}
            __threadfence();
        }
        gen = target;
    }
    __syncthreads();
}

// write h (single fp16) into B-fragment layout
__device__ __forceinline__ void store_h(uint32_t* bdst, int b, int hh, float hn) {
    int k16 = hh >> 4;
    int kc = hh & 15;
    int n8 = b >> 3;
    int nc = b & 7;
    int lane = nc * 4 + ((kc & 7) >> 1);
    int reg = (kc >= 8) ? 1 : 0;
    size_t bidx = (size_t)(((k16 * 4 + n8) * 32 + lane) * 2 + reg) * 2 + (kc & 1);
    ((__half*)bdst)[bidx] = __float2half_rn(hn);
}

// ---------------------------------------------------------------------------
// Persistent LSTM: 128 blocks x 256 threads, one grid barrier per step.
//   L0 (bid 0..63):  M=64 (16 hh), K=1024, A=Wh0 PINNED IN SMEM.
//     B staged in 2 commit-groups (quarters {0,2} then {1,3}) so the
//     second half's staging overlaps the first half's MMA.
//   L1 (bid 64..127): M=64, warps (mat, tile): Wh1 (SMEM-pinned) @ h1 and
//     Wx1 (streamed) @ h0 concurrently; B staged as 4x32KB chunks,
//     double-buffered (prefetch c+2 during MMA of c).
// Fused cell update per block; c state in SMEM; h double-buffered in gmem.
// ---------------------------------------------------------------------------
__global__ __launch_bounds__(256, 1) void lstm_persist(
    const float* __restrict__ Bias, float* __restrict__ out) {
    extern __shared__ uint32_t sm[];
    uint4* sA = (uint4*)sm;                      // 8192 u4 = 128 KB pinned A
    uint32_t* sB = sm + 32768;                   // 16384 b32 = 64 KB
    float* sTile = (float*)(sm + 49152);         // 2048 f32
    float* sC = sTile + 2048;                    // 512 f32

    int tid = threadIdx.x;
    int lane = tid & 31;
    int wrp = tid >> 5;
    int bid = blockIdx.x;
    int region = (bid < 64) ? 0 : 1;
    int blk = bid & 63;
    uint32_t sBaddr = smem_u32(sB);

    // preload pinned A slice (mat0 for L0, mat1=Wh1 for L1), 8192 uint4
    {
        const uint4* Apin = (const uint4*)g_Ahi +
            (size_t)region * MAT_U4 + (size_t)(blk * 4) * NK16 * 32;
        for (int i = tid; i < 8192; i += 256) sA[i] = Apin[i];
    }

    float bf[2], bw[2], bi_[2], bo[2];
#pragma unroll
    for (int i = 0; i < 2; i++) {
        int hh = blk * 16 + ((tid + i * 256) >> 5);
        int boff = region * 4096;
        bf[i] = Bias[boff + hh];        bw[i] = Bias[boff + 1024 + hh];
        bi_[i] = Bias[boff + 2048 + hh]; bo[i] = Bias[boff + 3072 + hh];
    }

    unsigned gen = 0;

    if (region == 0) {
        // prologue: h0(0) = cell(c=0, xg0[0] + bias) -> g_B0[0]
        const float* xg = g_xg0 + (size_t)(blk * 64) * 32;
#pragma unroll
        for (int i = 0; i < 2; i++) {
            int q = tid + i * 256;
            int hh_l = q >> 5, b = q & 31, br = hh_l * 4;
            float w = xg[(br + 1) * 32 + b] + bw[i];
            float i_ = xg[(br + 2) * 32 + b] + bi_[i];
            float o = xg[(br + 3) * 32 + b] + bo[i];
            float cn = sigf(w) * tanhfast(i_);
            float hn = tanhfast(cn) * sigf(o);
            sC[q] = cn;
            store_h(g_B0[0], b, blk * 16 + hh_l, hn);
        }
    } else {
#pragma unroll
        for (int i = 0; i < 2; i++) sC[tid + i * 256] = 0.0f;
    }
    __syncthreads();

    int tile = wrp & 3;
    int sel = wrp >> 2;        // L0: khalf ; L1: mat (0=Wh1@h1, 1=Wx1@h0)

    if (region == 0) {
        // ------------------------------ LAYER 0 ------------------------------
        for (int n = 0; n < NT; n++) {
            grid_sync(gen);
            if (n >= NT - 1) continue;          // no h0(512) needed
            int p = n & 1;

            // prefetch next-step input gates into registers (hide DRAM)
            float xr[8];
            {
                const float* xg = g_xg0 + (size_t)(n + 1) * GB + (size_t)(blk * 64) * 32;
#pragma unroll
                for (int i = 0; i < 2; i++) {
                    int q = tid + i * 256;
                    int b = q & 31, br = (q >> 5) * 4;
#pragma unroll
                    for (int g = 0; g < 4; g++)
                        xr[i * 4 + g] = xg[(br + g) * 32 + b];
                }
            }
            // stage h0(n) fragments in two commit groups:
            // group1 = quarters {0,2} (first k16 range of each khalf warp set)
            {
                const uint32_t* src = g_B0[p];
#pragma unroll
                for (int i = 0; i < 4; i++) {
                    int u = tid + i * 256;                       // 0..1023
                    cp16(sBaddr + u * 16, src + u * 4);                   // q0
                    cp16(sBaddr + (u + 2048) * 16, src + (u + 2048) * 4); // q2
                }
                CP_COMMIT();
#pragma unroll
                for (int i = 0; i < 4; i++) {
                    int u = tid + i * 256;
                    cp16(sBaddr + (u + 1024) * 16, src + (u + 1024) * 4); // q1
                    cp16(sBaddr + (u + 3072) * 16, src + (u + 3072) * 4); // q3
                }
                CP_COMMIT();
            }

            float acc[4][4];
#pragma unroll
            for (int nt = 0; nt < 4; nt++)
#pragma unroll
                for (int q = 0; q < 4; q++) acc[nt][q] = 0.0f;

            CP_WAIT1();                         // group1 (q0,q2) ready
            __syncthreads();
#pragma unroll 8
            for (int kk = 0; kk < 16; kk++) {
                int k16 = sel * 32 + kk;
                uint4 a = sA[(tile * 64 + k16) * 32 + lane];
#pragma unroll
                for (int nt = 0; nt < 4; nt++) {
                    int bix = (k16 * 4 + nt) * 64 + lane * 2;
                    mma_f16(acc[nt], a, sB[bix], sB[bix + 1]);
                }
            }
            CP_WAIT0();                         // group2 (q1,q3) ready
            __syncthreads();
#pragma unroll 8
            for (int kk = 16; kk < 32; kk++) {
                int k16 = sel * 32 + kk;
                uint4 a = sA[(tile * 64 + k16) * 32 + lane];
#pragma unroll
                for (int nt = 0; nt < 4; nt++) {
                    int bix = (k16 * 4 + nt) * 64 + lane * 2;
                    mma_f16(acc[nt], a, sB[bix], sB[bix + 1]);
                }
            }
            // combine K-halves in sTile
            int r0 = tile * 16 + (lane >> 2);
            int cc = (lane & 3) * 2;
            if (sel == 0) {
#pragma unroll
                for (int nt = 0; nt < 4; nt++) {
                    *(float2*)&sTile[r0 * 32 + nt * 8 + cc] =
                        make_float2(acc[nt][0], acc[nt][1]);
                    *(float2*)&sTile[(r0 + 8) * 32 + nt * 8 + cc] =
                        make_float2(acc[nt][2], acc[nt][3]);
                }
            }
            __syncthreads();
            if (sel == 1) {
#pragma unroll
                for (int nt = 0; nt < 4; nt++) {
                    float2* p0 = (float2*)&sTile[r0 * 32 + nt * 8 + cc];
                    float2* p1 = (float2*)&sTile[(r0 + 8) * 32 + nt * 8 + cc];
                    float2 v0 = *p0, v1 = *p1;
                    v0.x += acc[nt][0]; v0.y += acc[nt][1];
                    v1.x += acc[nt][2]; v1.y += acc[nt][3];
                    *p0 = v0; *p1 = v1;
                }
            }
            __syncthreads();
            // fused cell update -> h0(n+1)
#pragma unroll
            for (int i = 0; i < 2; i++) {
                int q = tid + i * 256;
                int hh_l = q >> 5, b = q & 31, br = hh_l * 4;
                float f = sTile[br * 32 + b] + xr[i * 4 + 0] + bf[i];
                float w = sTile[(br + 1) * 32 + b] + xr[i * 4 + 1] + bw[i];
                float i_ = sTile[(br + 2) * 32 + b] + xr[i * 4 + 2] + bi_[i];
                float o = sTile[(br + 3) * 32 + b] + xr[i * 4 + 3] + bo[i];
                float cv = sC[q];
                float cn = cv * sigf(f) + sigf(w) * tanhfast(i_);
                float hn = tanhfast(cn) * sigf(o);
                sC[q] = cn;
                store_h(g_B0[1 - p], b, blk * 16 + hh_l, hn);
            }
            __syncthreads();
        }
    } else {
        // ------------------------------ LAYER 1 ------------------------------
        const uint4* A2 = (const uint4*)g_Ahi + 2 * MAT_U4 +
            (size_t)(blk * 4 + tile) * NK16 * 32;   // Wx1 streamed

        for (int n = 0; n < NT; n++) {
            grid_sync(gen);
            int p = n & 1;
            const uint32_t* s1 = g_B1[p];
            const uint32_t* s0 = g_B0[p];

            // chunk c (k16 quarter): buf (c&1): [0:4096) h1, [4096:8192) h0
            auto prefetchq = [&](int c) {
                uint32_t dst = sBaddr + (c & 1) * 32768;
#pragma unroll
                for (int i = 0; i < 4; i++) {
                    int u = tid + i * 256;                  // 0..1023
                    cp16(dst + u * 16, s1 + c * 4096 + u * 4);
                    cp16(dst + 16384 + u * 16, s0 + c * 4096 + u * 4);
                }
                CP_COMMIT();
            };
            prefetchq(0);
            prefetchq(1);

            float acc[4][4];
#pragma unroll
            for (int nt = 0; nt < 4; nt++)
#pragma unroll
                for (int q = 0; q < 4; q++) acc[nt][q] = 0.0f;

            for (int c = 0; c < 4; c++) {
                if (c == 3) { CP_WAIT0(); } else { CP_WAIT1(); }
                __syncthreads();
                const uint32_t* myB = sB + (c & 1) * 8192 + sel * 4096;
#pragma unroll 8
                for (int kk = 0; kk < 16; kk++) {
                    int k16 = c * 16 + kk;
                    uint4 a = (sel == 0) ? sA[(tile * 64 + k16) * 32 + lane]
                                         : A2[k16 * 32 + lane];
#pragma unroll
                    for (int nt = 0; nt < 4; nt++) {
                        int bix = (kk * 4 + nt) * 64 + lane * 2;
                        mma_f16(acc[nt], a, myB[bix], myB[bix + 1]);
                    }
                }
                __syncthreads();            // all warps done with buf c&1
                if (c < 2) prefetchq(c + 2);
            }
            // combine the two matrices in sTile
            int r0 = tile * 16 + (lane >> 2);
            int cc = (lane & 3) * 2;
            if (sel == 0) {
#pragma unroll
                for (int nt = 0; nt < 4; nt++) {
                    *(float2*)&sTile[r0 * 32 + nt * 8 + cc] =
                        make_float2(acc[nt][0], acc[nt][1]);
                    *(float2*)&sTile[(r0 + 8) * 32 + nt * 8 + cc] =
                        make_float2(acc[nt][2], acc[nt][3]);
                }
            }
            __syncthreads();
            if (sel == 1) {
#pragma unroll
                for (int nt = 0; nt < 4; nt++) {
                    float2* p0 = (float2*)&sTile[r0 * 32 + nt * 8 + cc];
                    float2* p1 = (float2*)&sTile[(r0 + 8) * 32 + nt * 8 + cc];
                    float2 v0 = *p0, v1 = *p1;
                    v0.x += acc[nt][0]; v0.y += acc[nt][1];
                    v1.x += acc[nt][2]; v1.y += acc[nt][3];
                    *p0 = v0; *p1 = v1;
                }
            }
            __syncthreads();
            // fused cell update -> h1(n)
#pragma unroll
            for (int i = 0; i < 2; i++) {
                int q = tid + i * 256;
                int hh_l = q >> 5, b = q & 31, br = hh_l * 4;
                float f = sTile[br * 32 + b] + bf[i];
                float w = sTile[(br + 1) * 32 + b] + bw[i];
                float i_ = sTile[(br + 2) * 32 + b] + bi_[i];
                float o = sTile[(br + 3) * 32 + b] + bo[i];
                float cv = sC[q];
                float cn = cv * sigf(f) + sigf(w) * tanhfast(i_);
                float hn = tanhfast(cn) * sigf(o);
                sC[q] = cn;
                store_h(g_B1[1 - p], b, blk * 16 + hh_l, hn);
                if (n == NT - 1) out[b * 1024 + blk * 16 + hh_l] = hn;
            }
            __syncthreads();
        }
    }
}

// ---------------------------------------------------------------------------
extern "C" void kernel_launch(void* const* d_in, const int* in_sizes, int n_in,
                              void* d_out, int out_size) {
    const float* seq  = (const float*)d_in[0];  // (32, 512, 1024)
    const float* Wh   = (const float*)d_in[1];  // (2, 4, 1024, 1024)
    const float* Wx   = (const float*)d_in[2];  // (2, 4, 1024, 1024)
    const float* Bias = (const float*)d_in[3];  // (2, 4, 1024)
    float* out = (float*)d_out;                 // (32, 1024)

    cudaFuncSetAttribute(lstm_persist,
                         cudaFuncAttributeMaxDynamicSharedMemorySize, SMEM_BYTES);
    cudaFuncSetAttribute(pregemm_mma,
                         cudaFuncAttributeMaxDynamicSharedMemorySize, PRE_SMEM);

    init_state<<<64, 256>>>();
    prep_weights<<<4 * 4096 * 1024 / 256, 256>>>(Wh, Wx);
    prep_seq<<<NB * NT * NI / 256, 256>>>(seq);
    pregemm_mma<<<dim3(32, 128), 256, PRE_SMEM>>>();
    lstm_persist<<<GRID_BLOCKS, 256, SMEM_BYTES>>>(Bias, out);
}